// round 9
// baseline (speedup 1.0000x reference)
#include <cuda_runtime.h>

// ---------------------------------------------------------------------------
// One fused kernel. 256 threads/block, 4 batch elements per thread (512 blocks
// for B=524288). Per-block setup: coalesced smem staging of weights, then
// 2 warps derive the 8 scalar constants. 85-reg budget (launch_bounds 256,3)
// so the per-element math never spills.
// ---------------------------------------------------------------------------

#define P 33                      // padded row stride for Wi in smem
#define LOG2E 1.4426950408889634f
// sV offsets
#define V_QWA 0
#define V_BA  32
#define V_QWB 64
#define V_BB  96
#define V_WF  128
#define V_BOAB 160
#define V_BOBA 192
#define V_BIAB 224
#define V_BIBA 320

__device__ __forceinline__ void stage_scalar(
    int idx, float* sV, float* sC,
    const float* WA, const float* bA, const float* WB, const float* bB,
    const float* Wf, const float* bo_AB, const float* bo_BA,
    const float* bi_AB, const float* bi_BA, const float* bf)
{
    if (idx < 32)              sV[V_QWA + idx]        = WA[idx];
    else if (idx < 64)         sV[V_BA  + idx - 32]   = bA[idx - 32];
    else if (idx < 96)         sV[V_QWB + idx - 64]   = WB[idx - 64];
    else if (idx < 128)        sV[V_BB  + idx - 96]   = bB[idx - 96];
    else if (idx < 160)        sV[V_WF  + idx - 128]  = Wf[idx - 128];
    else if (idx < 192)        sV[V_BOAB + idx - 160] = bo_AB[idx - 160];
    else if (idx < 224)        sV[V_BOBA + idx - 192] = bo_BA[idx - 192];
    else if (idx < 320)        sV[V_BIAB + idx - 224] = bi_AB[idx - 224];
    else if (idx < 416)        sV[V_BIBA + idx - 320] = bi_BA[idx - 320];
    else if (idx == 416)       sC[8] = bf[0];
}

// Per-element closed form (exp2-folded):
//   S = b0 + db * mean3( 1/(1+exp2(fmaf(C0,a_i,C1)*ndb)) ),  ndb=(b0-b1)*log2e
//   T = 0.5 * sum_j (a0*u + a1 + a2*v)/(u+1+v),
//       u=exp2(wl*(a0-a1)), v=exp2(wl*(a2-a1)), wl=fmaf(C4,b_j,C5)*log2e
//   y = K0 + C2*S + C6*T ; leaky-relu(0.01)
__device__ __forceinline__ float elem_eval(
    float a0, float a1, float a2, float b0, float b1,
    float C0, float C1, float C2, float C4, float C5, float C6, float K0)
{
    const float db  = b1 - b0;
    const float ndb = -db * LOG2E;
    const float e0 = exp2f(fmaf(C0, a0, C1) * ndb);
    const float e1 = exp2f(fmaf(C0, a1, C1) * ndb);
    const float e2 = exp2f(fmaf(C0, a2, C1) * ndb);
    const float s0 = __fdividef(1.f, 1.f + e0);
    const float s1 = __fdividef(1.f, 1.f + e1);
    const float s2 = __fdividef(1.f, 1.f + e2);
    const float S  = fmaf(db, (s0 + s1 + s2) * (1.f / 3.f), b0);

    const float d01 = a0 - a1, d21 = a2 - a1;

    const float wl0 = fmaf(C4, b0, C5) * LOG2E;
    const float u0 = exp2f(wl0 * d01);
    const float v0 = exp2f(wl0 * d21);
    const float t0 = __fdividef(fmaf(a0, u0, fmaf(a2, v0, a1)), u0 + v0 + 1.f);

    const float wl1 = fmaf(C4, b1, C5) * LOG2E;
    const float u1 = exp2f(wl1 * d01);
    const float v1 = exp2f(wl1 * d21);
    const float t1 = __fdividef(fmaf(a0, u1, fmaf(a2, v1, a1)), u1 + v1 + 1.f);

    const float T = 0.5f * (t0 + t1);
    const float y = fmaf(C2, S, fmaf(C6, T, K0));
    return (y >= 0.f) ? y : 0.01f * y;
}

__global__ void __launch_bounds__(256, 3)
fused_kernel(const float* __restrict__ gA, const float* __restrict__ gB,
             const float* __restrict__ WA, const float* __restrict__ bA,
             const float* __restrict__ WB, const float* __restrict__ bB,
             const float* __restrict__ Wi_AB, const float* __restrict__ bi_AB,
             const float* __restrict__ Wo_AB, const float* __restrict__ bo_AB,
             const float* __restrict__ Wi_BA, const float* __restrict__ bi_BA,
             const float* __restrict__ Wo_BA, const float* __restrict__ bo_BA,
             const float* __restrict__ Wf, const float* __restrict__ bf,
             float* __restrict__ out, int nT, int B)
{
    __shared__ float smWi[2][96 * P];
    __shared__ float smWo[2][32 * 32];
    __shared__ float sV[417];
    __shared__ float sC[9];

    const int tid = threadIdx.x;
    const int t   = blockIdx.x * 256 + tid;     // group of 4 elements
    const bool act = t < nT;

    // ---- phase A: staging loads first (they gate the barrier) ----
    {
        const float4* src0 = (const float4*)Wi_AB;
        const float4* src1 = (const float4*)Wi_BA;
        #pragma unroll
        for (int k = tid; k < 768; k += 256) {
            const int r = k >> 3, c = (k & 7) << 2;
            float4 v = src0[k];
            float* d = &smWi[0][r * P + c];
            d[0] = v.x; d[1] = v.y; d[2] = v.z; d[3] = v.w;
            v = src1[k];
            d = &smWi[1][r * P + c];
            d[0] = v.x; d[1] = v.y; d[2] = v.z; d[3] = v.w;
        }
        // Wo: 512 float4 total across both dirs; 2 per thread.
        #pragma unroll
        for (int k = tid; k < 512; k += 256) {
            const int dir = k >> 8;
            const float4* src = dir ? (const float4*)Wo_BA : (const float4*)Wo_AB;
            ((float4*)smWo[dir])[k & 255] = src[k & 255];
        }
        stage_scalar(tid, sV, sC, WA, bA, WB, bB, Wf, bo_AB, bo_BA,
                     bi_AB, bi_BA, bf);
        stage_scalar(tid + 256, sV, sC, WA, bA, WB, bB, Wf, bo_AB, bo_BA,
                     bi_AB, bi_BA, bf);
    }

    // ---- batch-data loads (independent; land while setup proceeds) ----
    float4 A0, A1, A2, B0, B1;
    if (act) {
        const float4* gA4 = (const float4*)gA;
        const float4* gB4 = (const float4*)gB;
        A0 = gA4[3 * t]; A1 = gA4[3 * t + 1]; A2 = gA4[3 * t + 2];
        B0 = gB4[2 * t]; B1 = gB4[2 * t + 1];
    }
    __syncthreads();

    // ---- phase B: 2 warps derive the 8 scalar constants ----
    const int warp = tid >> 5;
    const int e    = tid & 31;
    if (warp < 2) {
        const int dir = warp;
        const int qw = dir ? V_QWB : V_QWA;
        const int qb = dir ? V_BB  : V_BA;
        const int kw = dir ? V_QWA : V_QWB;
        const int kb = dir ? V_BA  : V_BB;
        const int bi = dir ? V_BIBA : V_BIAB;
        const int bo = dir ? V_BOBA : V_BOAB;

        const float* rq = &smWi[dir][e * P];
        const float* rk = &smWi[dir][(32 + e) * P];
        const float* rv = &smWi[dir][(64 + e) * P];
        const float* wo = smWo[dir];

        float uq = 0.f, cq = 0.f, uk = 0.f, uv = 0.f, cv = 0.f, g = 0.f;
        #pragma unroll
        for (int d = 0; d < 32; ++d) {
            const float wq = rq[d], wkv = rk[d], wvv = rv[d];
            uq = fmaf(wq,  sV[qw + d], uq);
            cq = fmaf(wq,  sV[qb + d], cq);
            uk = fmaf(wkv, sV[kw + d], uk);
            uv = fmaf(wvv, sV[kw + d], uv);
            cv = fmaf(wvv, sV[kb + d], cv);
            g  = fmaf(sV[V_WF + d], wo[d * 32 + e], g);
        }
        cq += sV[bi + e];
        cv += sV[bi + 64 + e];

        float alpha = uq * uk;
        float gamma = cq * uk;
        float kk    = g * uv;
        float rr    = fmaf(sV[V_WF + e], sV[bo + e], g * cv);
        #pragma unroll
        for (int off = 16; off; off >>= 1) {
            alpha += __shfl_xor_sync(0xffffffffu, alpha, off);
            gamma += __shfl_xor_sync(0xffffffffu, gamma, off);
            kk    += __shfl_xor_sync(0xffffffffu, kk, off);
            rr    += __shfl_xor_sync(0xffffffffu, rr, off);
        }
        if (e == 0) {
            const float inv_sqrtE = 0.17677669529663688f;  // 1/sqrt(32)
            sC[dir * 4 + 0] = alpha * inv_sqrtE;
            sC[dir * 4 + 1] = gamma * inv_sqrtE;
            sC[dir * 4 + 2] = 0.5f * kk;
            sC[dir * 4 + 3] = rr;
        }
    }
    __syncthreads();

    const float C0 = sC[0], C1 = sC[1], C2 = sC[2], C3 = sC[3];
    const float C4 = sC[4], C5 = sC[5], C6 = sC[6], C7 = sC[7];
    const float K0 = fmaf(0.5f, C3 + C7, sC[8]);

    // ---- main compute: 4 elements, fully scalar ----
    if (act) {
        const float r0 = elem_eval(A0.x, A0.y, A0.z, B0.x, B0.y,
                                   C0, C1, C2, C4, C5, C6, K0);
        const float r1 = elem_eval(A0.w, A1.x, A1.y, B0.z, B0.w,
                                   C0, C1, C2, C4, C5, C6, K0);
        const float r2 = elem_eval(A1.z, A1.w, A2.x, B1.x, B1.y,
                                   C0, C1, C2, C4, C5, C6, K0);
        const float r3 = elem_eval(A2.y, A2.z, A2.w, B1.z, B1.w,
                                   C0, C1, C2, C4, C5, C6, K0);
        ((float4*)out)[t] = make_float4(r0, r1, r2, r3);
    }

    // tail for B % 4 != 0 (dead for B = 524288)
    if (blockIdx.x == 0 && tid == 0 && (B & 3)) {
        for (int idx = nT * 4; idx < B; ++idx) {
            out[idx] = elem_eval(gA[3 * idx], gA[3 * idx + 1], gA[3 * idx + 2],
                                 gB[2 * idx], gB[2 * idx + 1],
                                 C0, C1, C2, C4, C5, C6, K0);
        }
    }
}

extern "C" void kernel_launch(void* const* d_in, const int* in_sizes, int n_in,
                              void* d_out, int out_size)
{
    const float* gA    = (const float*)d_in[0];   // [B,3]
    const float* gB    = (const float*)d_in[1];   // [B,2]
    const float* WA    = (const float*)d_in[2];   // [32,1]
    const float* bA    = (const float*)d_in[3];   // [32]
    const float* WB    = (const float*)d_in[4];
    const float* bB    = (const float*)d_in[5];
    const float* Wi_AB = (const float*)d_in[6];   // [96,32]
    const float* bi_AB = (const float*)d_in[7];   // [96]
    const float* Wo_AB = (const float*)d_in[8];   // [32,32]
    const float* bo_AB = (const float*)d_in[9];   // [32]
    const float* Wi_BA = (const float*)d_in[10];
    const float* bi_BA = (const float*)d_in[11];
    const float* Wo_BA = (const float*)d_in[12];
    const float* bo_BA = (const float*)d_in[13];
    const float* Wf    = (const float*)d_in[14];  // [1,32]
    const float* bf    = (const float*)d_in[15];  // [1]

    const int B  = in_sizes[0] / 3;
    const int nT = B / 4;                          // groups of 4 elements
    int grid = (nT + 255) / 256;
    if (grid < 1) grid = 1;

    fused_kernel<<<grid, 256>>>(gA, gB, WA, bA, WB, bB,
                                Wi_AB, bi_AB, Wo_AB, bo_AB,
                                Wi_BA, bi_BA, Wo_BA, bo_BA,
                                Wf, bf, (float*)d_out, nT, B);
}

// round 10
// speedup vs baseline: 1.0269x; 1.0269x over previous
#include <cuda_runtime.h>

// ---------------------------------------------------------------------------
// One fused kernel. 256 threads/block, 8 batch elements per thread (256 blocks
// for B=524288). Smem staging of weights + 2-warp constant derivation, then
// closed-form evaluation. launch_bounds(256,3): 85-reg budget -> no spills.
// ---------------------------------------------------------------------------

#define P 33                      // padded row stride for Wi in smem
#define LOG2E 1.4426950408889634f
// sV offsets
#define V_QWA 0
#define V_BA  32
#define V_QWB 64
#define V_BB  96
#define V_WF  128
#define V_BOAB 160
#define V_BOBA 192
#define V_BIAB 224
#define V_BIBA 320

__device__ __forceinline__ void stage_scalar(
    int idx, float* sV, float* sC,
    const float* WA, const float* bA, const float* WB, const float* bB,
    const float* Wf, const float* bo_AB, const float* bo_BA,
    const float* bi_AB, const float* bi_BA, const float* bf)
{
    if (idx < 32)              sV[V_QWA + idx]        = WA[idx];
    else if (idx < 64)         sV[V_BA  + idx - 32]   = bA[idx - 32];
    else if (idx < 96)         sV[V_QWB + idx - 64]   = WB[idx - 64];
    else if (idx < 128)        sV[V_BB  + idx - 96]   = bB[idx - 96];
    else if (idx < 160)        sV[V_WF  + idx - 128]  = Wf[idx - 128];
    else if (idx < 192)        sV[V_BOAB + idx - 160] = bo_AB[idx - 160];
    else if (idx < 224)        sV[V_BOBA + idx - 192] = bo_BA[idx - 192];
    else if (idx < 320)        sV[V_BIAB + idx - 224] = bi_AB[idx - 224];
    else if (idx < 416)        sV[V_BIBA + idx - 320] = bi_BA[idx - 320];
    else if (idx == 416)       sC[8] = bf[0];
}

// Per-element closed form (exp2-folded).
__device__ __forceinline__ float elem_eval(
    float a0, float a1, float a2, float b0, float b1,
    float C0, float C1, float C2, float C4, float C5, float C6, float K0)
{
    const float db  = b1 - b0;
    const float ndb = -db * LOG2E;
    const float e0 = exp2f(fmaf(C0, a0, C1) * ndb);
    const float e1 = exp2f(fmaf(C0, a1, C1) * ndb);
    const float e2 = exp2f(fmaf(C0, a2, C1) * ndb);
    const float s0 = __fdividef(1.f, 1.f + e0);
    const float s1 = __fdividef(1.f, 1.f + e1);
    const float s2 = __fdividef(1.f, 1.f + e2);
    const float S  = fmaf(db, (s0 + s1 + s2) * (1.f / 3.f), b0);

    const float d01 = a0 - a1, d21 = a2 - a1;

    const float wl0 = fmaf(C4, b0, C5) * LOG2E;
    const float u0 = exp2f(wl0 * d01);
    const float v0 = exp2f(wl0 * d21);
    const float t0 = __fdividef(fmaf(a0, u0, fmaf(a2, v0, a1)), u0 + v0 + 1.f);

    const float wl1 = fmaf(C4, b1, C5) * LOG2E;
    const float u1 = exp2f(wl1 * d01);
    const float v1 = exp2f(wl1 * d21);
    const float t1 = __fdividef(fmaf(a0, u1, fmaf(a2, v1, a1)), u1 + v1 + 1.f);

    const float T = 0.5f * (t0 + t1);
    const float y = fmaf(C2, S, fmaf(C6, T, K0));
    return (y >= 0.f) ? y : 0.01f * y;
}

__global__ void __launch_bounds__(256, 3)
fused_kernel(const float* __restrict__ gA, const float* __restrict__ gB,
             const float* __restrict__ WA, const float* __restrict__ bA,
             const float* __restrict__ WB, const float* __restrict__ bB,
             const float* __restrict__ Wi_AB, const float* __restrict__ bi_AB,
             const float* __restrict__ Wo_AB, const float* __restrict__ bo_AB,
             const float* __restrict__ Wi_BA, const float* __restrict__ bi_BA,
             const float* __restrict__ Wo_BA, const float* __restrict__ bo_BA,
             const float* __restrict__ Wf, const float* __restrict__ bf,
             float* __restrict__ out, int nT, int B)
{
    __shared__ float smWi[2][96 * P];
    __shared__ float smWo[2][32 * 32];
    __shared__ float sV[417];
    __shared__ float sC[9];

    const int tid = threadIdx.x;
    const int t   = blockIdx.x * 256 + tid;     // group of 8 elements
    const bool act = t < nT;

    // ---- phase A: staging loads first (they gate the barrier) ----
    {
        const float4* src0 = (const float4*)Wi_AB;
        const float4* src1 = (const float4*)Wi_BA;
        #pragma unroll
        for (int k = tid; k < 768; k += 256) {
            const int r = k >> 3, c = (k & 7) << 2;
            float4 v = src0[k];
            float* d = &smWi[0][r * P + c];
            d[0] = v.x; d[1] = v.y; d[2] = v.z; d[3] = v.w;
            v = src1[k];
            d = &smWi[1][r * P + c];
            d[0] = v.x; d[1] = v.y; d[2] = v.z; d[3] = v.w;
        }
        #pragma unroll
        for (int k = tid; k < 512; k += 256) {
            const int dir = k >> 8;
            const float4* src = dir ? (const float4*)Wo_BA : (const float4*)Wo_AB;
            ((float4*)smWo[dir])[k & 255] = src[k & 255];
        }
        stage_scalar(tid, sV, sC, WA, bA, WB, bB, Wf, bo_AB, bo_BA,
                     bi_AB, bi_BA, bf);
        stage_scalar(tid + 256, sV, sC, WA, bA, WB, bB, Wf, bo_AB, bo_BA,
                     bi_AB, bi_BA, bf);
    }

    // ---- batch-data loads (10x LDG.128; land while setup proceeds) ----
    float4 Aa, Ab, Ac, Ad, Ae, Af, Ba, Bb, Bc, Bd;
    if (act) {
        const float4* gA4 = (const float4*)gA;   // 6 float4 per thread-group
        const float4* gB4 = (const float4*)gB;   // 4 float4 per thread-group
        Aa = gA4[6 * t];     Ab = gA4[6 * t + 1]; Ac = gA4[6 * t + 2];
        Ad = gA4[6 * t + 3]; Ae = gA4[6 * t + 4]; Af = gA4[6 * t + 5];
        Ba = gB4[4 * t];     Bb = gB4[4 * t + 1];
        Bc = gB4[4 * t + 2]; Bd = gB4[4 * t + 3];
    }
    __syncthreads();

    // ---- phase B: 2 warps derive the 8 scalar constants ----
    const int warp = tid >> 5;
    const int e    = tid & 31;
    if (warp < 2) {
        const int dir = warp;
        const int qw = dir ? V_QWB : V_QWA;
        const int qb = dir ? V_BB  : V_BA;
        const int kw = dir ? V_QWA : V_QWB;
        const int kb = dir ? V_BA  : V_BB;
        const int bi = dir ? V_BIBA : V_BIAB;
        const int bo = dir ? V_BOBA : V_BOAB;

        const float* rq = &smWi[dir][e * P];
        const float* rk = &smWi[dir][(32 + e) * P];
        const float* rv = &smWi[dir][(64 + e) * P];
        const float* wo = smWo[dir];

        float uq = 0.f, cq = 0.f, uk = 0.f, uv = 0.f, cv = 0.f, g = 0.f;
        #pragma unroll
        for (int d = 0; d < 32; ++d) {
            const float wq = rq[d], wkv = rk[d], wvv = rv[d];
            uq = fmaf(wq,  sV[qw + d], uq);
            cq = fmaf(wq,  sV[qb + d], cq);
            uk = fmaf(wkv, sV[kw + d], uk);
            uv = fmaf(wvv, sV[kw + d], uv);
            cv = fmaf(wvv, sV[kb + d], cv);
            g  = fmaf(sV[V_WF + d], wo[d * 32 + e], g);
        }
        cq += sV[bi + e];
        cv += sV[bi + 64 + e];

        float alpha = uq * uk;
        float gamma = cq * uk;
        float kk    = g * uv;
        float rr    = fmaf(sV[V_WF + e], sV[bo + e], g * cv);
        #pragma unroll
        for (int off = 16; off; off >>= 1) {
            alpha += __shfl_xor_sync(0xffffffffu, alpha, off);
            gamma += __shfl_xor_sync(0xffffffffu, gamma, off);
            kk    += __shfl_xor_sync(0xffffffffu, kk, off);
            rr    += __shfl_xor_sync(0xffffffffu, rr, off);
        }
        if (e == 0) {
            const float inv_sqrtE = 0.17677669529663688f;  // 1/sqrt(32)
            sC[dir * 4 + 0] = alpha * inv_sqrtE;
            sC[dir * 4 + 1] = gamma * inv_sqrtE;
            sC[dir * 4 + 2] = 0.5f * kk;
            sC[dir * 4 + 3] = rr;
        }
    }
    __syncthreads();

    const float C0 = sC[0], C1 = sC[1], C2 = sC[2], C3 = sC[3];
    const float C4 = sC[4], C5 = sC[5], C6 = sC[6], C7 = sC[7];
    const float K0 = fmaf(0.5f, C3 + C7, sC[8]);

    // ---- main compute: 8 elements, fully scalar ----
    if (act) {
        float4 o0, o1;
        o0.x = elem_eval(Aa.x, Aa.y, Aa.z, Ba.x, Ba.y, C0, C1, C2, C4, C5, C6, K0);
        o0.y = elem_eval(Aa.w, Ab.x, Ab.y, Ba.z, Ba.w, C0, C1, C2, C4, C5, C6, K0);
        o0.z = elem_eval(Ab.z, Ab.w, Ac.x, Bb.x, Bb.y, C0, C1, C2, C4, C5, C6, K0);
        o0.w = elem_eval(Ac.y, Ac.z, Ac.w, Bb.z, Bb.w, C0, C1, C2, C4, C5, C6, K0);
        o1.x = elem_eval(Ad.x, Ad.y, Ad.z, Bc.x, Bc.y, C0, C1, C2, C4, C5, C6, K0);
        o1.y = elem_eval(Ad.w, Ae.x, Ae.y, Bc.z, Bc.w, C0, C1, C2, C4, C5, C6, K0);
        o1.z = elem_eval(Ae.z, Ae.w, Af.x, Bd.x, Bd.y, C0, C1, C2, C4, C5, C6, K0);
        o1.w = elem_eval(Af.y, Af.z, Af.w, Bd.z, Bd.w, C0, C1, C2, C4, C5, C6, K0);
        ((float4*)out)[2 * t]     = o0;
        ((float4*)out)[2 * t + 1] = o1;
    }

    // tail for B % 8 != 0 (dead for B = 524288)
    if (blockIdx.x == 0 && tid == 0 && (B & 7)) {
        for (int idx = nT * 8; idx < B; ++idx) {
            out[idx] = elem_eval(gA[3 * idx], gA[3 * idx + 1], gA[3 * idx + 2],
                                 gB[2 * idx], gB[2 * idx + 1],
                                 C0, C1, C2, C4, C5, C6, K0);
        }
    }
}

extern "C" void kernel_launch(void* const* d_in, const int* in_sizes, int n_in,
                              void* d_out, int out_size)
{
    const float* gA    = (const float*)d_in[0];   // [B,3]
    const float* gB    = (const float*)d_in[1];   // [B,2]
    const float* WA    = (const float*)d_in[2];   // [32,1]
    const float* bA    = (const float*)d_in[3];   // [32]
    const float* WB    = (const float*)d_in[4];
    const float* bB    = (const float*)d_in[5];
    const float* Wi_AB = (const float*)d_in[6];   // [96,32]
    const float* bi_AB = (const float*)d_in[7];   // [96]
    const float* Wo_AB = (const float*)d_in[8];   // [32,32]
    const float* bo_AB = (const float*)d_in[9];   // [32]
    const float* Wi_BA = (const float*)d_in[10];
    const float* bi_BA = (const float*)d_in[11];
    const float* Wo_BA = (const float*)d_in[12];
    const float* bo_BA = (const float*)d_in[13];
    const float* Wf    = (const float*)d_in[14];  // [1,32]
    const float* bf    = (const float*)d_in[15];  // [1]

    const int B  = in_sizes[0] / 3;
    const int nT = B / 8;                          // groups of 8 elements
    int grid = (nT + 255) / 256;
    if (grid < 1) grid = 1;

    fused_kernel<<<grid, 256>>>(gA, gB, WA, bA, WB, bB,
                                Wi_AB, bi_AB, Wo_AB, bo_AB,
                                Wi_BA, bi_BA, Wo_BA, bo_BA,
                                Wf, bf, (float*)d_out, nT, B);
}

// round 11
// speedup vs baseline: 1.2704x; 1.2370x over previous
#include <cuda_runtime.h>

#define P 33                      // padded row stride for Wi in smem
#define LOG2E 1.4426950408889634f
// sV offsets
#define V_QWA 0
#define V_BA  32
#define V_QWB 64
#define V_BB  96
#define V_WF  128
#define V_BOAB 160
#define V_BOBA 192
#define V_BIAB 224
#define V_BIBA 320

__device__ __forceinline__ void stage_scalar(
    int idx, float* sV, float* sC,
    const float* WA, const float* bA, const float* WB, const float* bB,
    const float* Wf, const float* bo_AB, const float* bo_BA,
    const float* bi_AB, const float* bi_BA, const float* bf)
{
    if (idx < 32)              sV[V_QWA + idx]        = WA[idx];
    else if (idx < 64)         sV[V_BA  + idx - 32]   = bA[idx - 32];
    else if (idx < 96)         sV[V_QWB + idx - 64]   = WB[idx - 64];
    else if (idx < 128)        sV[V_BB  + idx - 96]   = bB[idx - 96];
    else if (idx < 160)        sV[V_WF  + idx - 128]  = Wf[idx - 128];
    else if (idx < 192)        sV[V_BOAB + idx - 160] = bo_AB[idx - 160];
    else if (idx < 224)        sV[V_BOBA + idx - 192] = bo_BA[idx - 192];
    else if (idx < 320)        sV[V_BIAB + idx - 224] = bi_AB[idx - 224];
    else if (idx < 416)        sV[V_BIBA + idx - 320] = bi_BA[idx - 320];
    else if (idx == 416)       sC[8] = bf[0];
}

// Closed form with pre-folded constants (C0l..C5l include log2e; C6h = 0.5*C6):
//   sigmoid-sum via one divide; 2-query softmax-sum via one divide.
__device__ __forceinline__ float elem_eval2(
    float a0, float a1, float a2, float b0, float b1,
    float C0l, float C1l, float C2, float C4l, float C5l, float C6h, float K0)
{
    const float db  = b1 - b0;
    const float mdb = -db;
    const float e0 = exp2f(fmaf(C0l, a0, C1l) * mdb);
    const float e1 = exp2f(fmaf(C0l, a1, C1l) * mdb);
    const float e2 = exp2f(fmaf(C0l, a2, C1l) * mdb);
    const float f0 = 1.f + e0, f1 = 1.f + e1, f2 = 1.f + e2;
    const float f01 = f0 * f1, f12 = f1 * f2, f02 = f0 * f2;
    const float sS  = __fdividef(f01 + f12 + f02, f01 * f2);   // s0+s1+s2
    const float S   = fmaf(db * (1.f / 3.f), sS, b0);

    const float d01 = a0 - a1, d21 = a2 - a1;
    const float wl0 = fmaf(C4l, b0, C5l);
    const float wl1 = fmaf(C4l, b1, C5l);
    const float u0 = exp2f(wl0 * d01), v0 = exp2f(wl0 * d21);
    const float u1 = exp2f(wl1 * d01), v1 = exp2f(wl1 * d21);
    const float n0 = fmaf(a0, u0, fmaf(a2, v0, a1));
    const float n1 = fmaf(a0, u1, fmaf(a2, v1, a1));
    const float dd0 = u0 + v0 + 1.f;
    const float dd1 = u1 + v1 + 1.f;
    const float Tn  = __fdividef(fmaf(n0, dd1, n1 * dd0), dd0 * dd1); // t0+t1

    const float y = fmaf(C2, S, fmaf(C6h, Tn, K0));
    return fmaxf(y, 0.01f * y);   // leaky-relu(0.01)
}

__global__ void __launch_bounds__(256, 3)
fused_kernel(const float* __restrict__ gA, const float* __restrict__ gB,
             const float* __restrict__ WA, const float* __restrict__ bA,
             const float* __restrict__ WB, const float* __restrict__ bB,
             const float* __restrict__ Wi_AB, const float* __restrict__ bi_AB,
             const float* __restrict__ Wo_AB, const float* __restrict__ bo_AB,
             const float* __restrict__ Wi_BA, const float* __restrict__ bi_BA,
             const float* __restrict__ Wo_BA, const float* __restrict__ bo_BA,
             const float* __restrict__ Wf, const float* __restrict__ bf,
             float* __restrict__ out, int B)
{
    __shared__ float smWi[2][96 * P];   // 25.3 KB
    __shared__ float sA[3072];          // 12 KB  (one A chunk: 1024 elements)
    __shared__ float sV[417];
    __shared__ float sC[9];

    const int tid = threadIdx.x;
    const int Eb  = blockIdx.x * 2048;          // first element of this block
    const int FA  = blockIdx.x * 1536;          // first float4 of A for block
    const int nA4 = (3 * B) >> 2;               // whole float4s in gA

    // ---- phase A: coalesced staging ----
    {
        const float4* src0 = (const float4*)Wi_AB;
        const float4* src1 = (const float4*)Wi_BA;
        #pragma unroll
        for (int k = tid; k < 768; k += 256) {
            const int r = k >> 3, c = (k & 7) << 2;
            float4 v = src0[k];
            float* d = &smWi[0][r * P + c];
            d[0] = v.x; d[1] = v.y; d[2] = v.z; d[3] = v.w;
            v = src1[k];
            d = &smWi[1][r * P + c];
            d[0] = v.x; d[1] = v.y; d[2] = v.z; d[3] = v.w;
        }
        stage_scalar(tid, sV, sC, WA, bA, WB, bB, Wf, bo_AB, bo_BA,
                     bi_AB, bi_BA, bf);
        stage_scalar(tid + 256, sV, sC, WA, bA, WB, bB, Wf, bo_AB, bo_BA,
                     bi_AB, bi_BA, bf);
    }
    // A chunk 1 -> smem (perfectly coalesced float4 loads)
    {
        const float4* gA4 = (const float4*)gA;
        #pragma unroll
        for (int j = 0; j < 3; ++j) {
            const int fi = FA + tid + 256 * j;
            float4 v = make_float4(0.f, 0.f, 0.f, 0.f);
            if (fi < nA4) v = gA4[fi];
            ((float4*)sA)[tid + 256 * j] = v;
        }
    }
    // Prefetch A chunk 2 (regs) + all B (coalesced float2)
    float4 Pa0, Pa1, Pa2;
    {
        const float4* gA4 = (const float4*)gA;
        Pa0 = make_float4(0.f,0.f,0.f,0.f);
        Pa1 = Pa0; Pa2 = Pa0;
        const int f0 = FA + 768 + tid;
        if (f0 < nA4)        Pa0 = gA4[f0];
        if (f0 + 256 < nA4)  Pa1 = gA4[f0 + 256];
        if (f0 + 512 < nA4)  Pa2 = gA4[f0 + 512];
    }
    float2 Bg[8];
    {
        const float2* gB2 = (const float2*)gB;
        #pragma unroll
        for (int g = 0; g < 8; ++g) {
            const int idx = Eb + 256 * g + tid;
            Bg[g] = (idx < B) ? gB2[idx] : make_float2(0.f, 0.f);
        }
    }
    __syncthreads();

    // ---- phase B: 2 warps derive the 8 scalar constants ----
    if (tid < 64) {
        const int dir = tid >> 5;
        const int e   = tid & 31;
        const int qw = dir ? V_QWB : V_QWA;
        const int qb = dir ? V_BB  : V_BA;
        const int kw = dir ? V_QWA : V_QWB;
        const int kb = dir ? V_BA  : V_BB;
        const int bi = dir ? V_BIBA : V_BIAB;
        const int bo = dir ? V_BOBA : V_BOAB;
        const float* Wo = dir ? Wo_BA : Wo_AB;

        const float* rq = &smWi[dir][e * P];
        const float* rk = &smWi[dir][(32 + e) * P];
        const float* rv = &smWi[dir][(64 + e) * P];

        float uq = 0.f, cq = 0.f, uk = 0.f, uv = 0.f, cv = 0.f, g = 0.f;
        #pragma unroll
        for (int d = 0; d < 32; ++d) {
            const float wq = rq[d], wkv = rk[d], wvv = rv[d];
            uq = fmaf(wq,  sV[qw + d], uq);
            cq = fmaf(wq,  sV[qb + d], cq);
            uk = fmaf(wkv, sV[kw + d], uk);
            uv = fmaf(wvv, sV[kw + d], uv);
            cv = fmaf(wvv, sV[kb + d], cv);
            g  = fmaf(sV[V_WF + d], Wo[d * 32 + e], g);  // coalesced across e
        }
        cq += sV[bi + e];
        cv += sV[bi + 64 + e];

        float alpha = uq * uk;
        float gamma = cq * uk;
        float kk    = g * uv;
        float rr    = fmaf(sV[V_WF + e], sV[bo + e], g * cv);
        #pragma unroll
        for (int off = 16; off; off >>= 1) {
            alpha += __shfl_xor_sync(0xffffffffu, alpha, off);
            gamma += __shfl_xor_sync(0xffffffffu, gamma, off);
            kk    += __shfl_xor_sync(0xffffffffu, kk, off);
            rr    += __shfl_xor_sync(0xffffffffu, rr, off);
        }
        if (e == 0) {
            const float inv_sqrtE = 0.17677669529663688f;  // 1/sqrt(32)
            sC[dir * 4 + 0] = alpha * inv_sqrtE;
            sC[dir * 4 + 1] = gamma * inv_sqrtE;
            sC[dir * 4 + 2] = 0.5f * kk;
            sC[dir * 4 + 3] = rr;
        }
    }
    __syncthreads();

    const float C0l = sC[0] * LOG2E, C1l = sC[1] * LOG2E;
    const float C2  = sC[2];
    const float C4l = sC[4] * LOG2E, C5l = sC[5] * LOG2E;
    const float C6h = 0.5f * sC[6];
    const float K0  = fmaf(0.5f, sC[3] + sC[7], sC[8]);

    // ---- chunk 1: elements Eb + [0,1024), conflict-free scalar LDS ----
    #pragma unroll
    for (int g = 0; g < 4; ++g) {
        const int i   = 256 * g + tid;
        const int idx = Eb + i;
        if (idx < B) {
            const float a0 = sA[3 * i], a1 = sA[3 * i + 1], a2 = sA[3 * i + 2];
            out[idx] = elem_eval2(a0, a1, a2, Bg[g].x, Bg[g].y,
                                  C0l, C1l, C2, C4l, C5l, C6h, K0);
        }
    }
    __syncthreads();

    // ---- swap in chunk 2 (prefetched) ----
    ((float4*)sA)[tid]       = Pa0;
    ((float4*)sA)[tid + 256] = Pa1;
    ((float4*)sA)[tid + 512] = Pa2;
    __syncthreads();

    // ---- chunk 2: elements Eb + [1024,2048) ----
    #pragma unroll
    for (int g = 0; g < 4; ++g) {
        const int i   = 256 * g + tid;
        const int idx = Eb + 1024 + i;
        if (idx < B) {
            const float a0 = sA[3 * i], a1 = sA[3 * i + 1], a2 = sA[3 * i + 2];
            out[idx] = elem_eval2(a0, a1, a2, Bg[4 + g].x, Bg[4 + g].y,
                                  C0l, C1l, C2, C4l, C5l, C6h, K0);
        }
    }

    // scalar tail if 3*B isn't float4-aligned (dead for B = 524288)
    if ((3 * B) & 3) {
        if (blockIdx.x == 0 && tid == 0) {
            for (int idx = (nA4 * 4) / 3; idx < B; ++idx) {
                out[idx] = elem_eval2(
                    gA[3 * idx], gA[3 * idx + 1], gA[3 * idx + 2],
                    gB[2 * idx], gB[2 * idx + 1],
                    C0l, C1l, C2, C4l, C5l, C6h, K0);
            }
        }
    }
}

extern "C" void kernel_launch(void* const* d_in, const int* in_sizes, int n_in,
                              void* d_out, int out_size)
{
    const float* gA    = (const float*)d_in[0];   // [B,3]
    const float* gB    = (const float*)d_in[1];   // [B,2]
    const float* WA    = (const float*)d_in[2];   // [32,1]
    const float* bA    = (const float*)d_in[3];   // [32]
    const float* WB    = (const float*)d_in[4];
    const float* bB    = (const float*)d_in[5];
    const float* Wi_AB = (const float*)d_in[6];   // [96,32]
    const float* bi_AB = (const float*)d_in[7];   // [96]
    const float* Wo_AB = (const float*)d_in[8];   // [32,32]
    const float* bo_AB = (const float*)d_in[9];   // [32]
    const float* Wi_BA = (const float*)d_in[10];
    const float* bi_BA = (const float*)d_in[11];
    const float* Wo_BA = (const float*)d_in[12];
    const float* bo_BA = (const float*)d_in[13];
    const float* Wf    = (const float*)d_in[14];  // [1,32]
    const float* bf    = (const float*)d_in[15];  // [1]

    const int B = in_sizes[0] / 3;
    int grid = (B + 2047) / 2048;
    if (grid < 1) grid = 1;

    fused_kernel<<<grid, 256>>>(gA, gB, WA, bA, WB, bB,
                                Wi_AB, bi_AB, Wo_AB, bo_AB,
                                Wi_BA, bi_BA, Wo_BA, bo_BA,
                                Wf, bf, (float*)d_out, B);
}